// round 1
// baseline (speedup 1.0000x reference)
#include <cuda_runtime.h>
#include <math.h>

#define BATCH 4
#define LSEQ 4096
#define DMdl 512
#define DIn 1024
#define DSt 16
#define DTRk 32
#define KCV 4
#define MROWS (BATCH * LSEQ)      // 16384
#define NCH 32                    // scan chunks
#define CHL (LSEQ / NCH)          // 128 steps per chunk

// ---------------- scratch (static device globals; no allocation) ----------------
__device__ float g_hn[MROWS * DMdl];          // layernorm output
__device__ float g_xz[MROWS * 2 * DIn];       // in_proj output (xq | z)
__device__ float g_xc[MROWS * DIn];           // conv+silu output
__device__ float g_dbl[MROWS * 64];           // xproj output (dtr|B|C)
__device__ float g_dt[MROWS * DIn];           // softplus(dt)
__device__ float g_y[MROWS * DIn];            // scan output (pre out_proj)
__device__ float g_h[MROWS * DMdl];           // layer output (residualless)
__device__ float g_P[BATCH * NCH * DSt * DIn];
__device__ float g_E[BATCH * NCH * DSt * DIn];
__device__ float g_H0[BATCH * NCH * DSt * DIn];

__device__ __forceinline__ float sigmoidf_(float v) {
    return 1.0f / (1.0f + __expf(-v));
}
__device__ __forceinline__ float softplusf_(float v) {
    return fmaxf(v, 0.0f) + log1pf(__expf(-fabsf(v)));
}

// ---------------- LayerNorm: one warp per row of 512 ----------------
__global__ __launch_bounds__(256) void layernorm_kernel(
    const float* __restrict__ x, const float* __restrict__ w,
    const float* __restrict__ bvec, float* __restrict__ out) {
    int warp = threadIdx.x >> 5, lane = threadIdx.x & 31;
    int row = blockIdx.x * 8 + warp;
    const float4* xr = reinterpret_cast<const float4*>(x + (size_t)row * DMdl);
    float4 v[4];
    float s = 0.0f;
#pragma unroll
    for (int j = 0; j < 4; j++) {
        v[j] = xr[j * 32 + lane];
        s += v[j].x + v[j].y + v[j].z + v[j].w;
    }
#pragma unroll
    for (int m = 16; m; m >>= 1) s += __shfl_xor_sync(0xffffffffu, s, m);
    float mean = s * (1.0f / DMdl);
    float vs = 0.0f;
#pragma unroll
    for (int j = 0; j < 4; j++) {
        float a = v[j].x - mean, b = v[j].y - mean, c = v[j].z - mean, d = v[j].w - mean;
        vs += a * a + b * b + c * c + d * d;
    }
#pragma unroll
    for (int m = 16; m; m >>= 1) vs += __shfl_xor_sync(0xffffffffu, vs, m);
    float rstd = rsqrtf(vs * (1.0f / DMdl) + 1e-5f);
    const float4* w4 = reinterpret_cast<const float4*>(w);
    const float4* b4 = reinterpret_cast<const float4*>(bvec);
    float4* o4 = reinterpret_cast<float4*>(out + (size_t)row * DMdl);
#pragma unroll
    for (int j = 0; j < 4; j++) {
        float4 wv = w4[j * 32 + lane], bv = b4[j * 32 + lane], r;
        r.x = (v[j].x - mean) * rstd * wv.x + bv.x;
        r.y = (v[j].y - mean) * rstd * wv.y + bv.y;
        r.z = (v[j].z - mean) * rstd * wv.z + bv.z;
        r.w = (v[j].w - mean) * rstd * wv.w + bv.w;
        o4[j * 32 + lane] = r;
    }
}

// ---------------- SGEMM (TN): C[m,n] = sum_k A[m,k]*B[n,k]  ----------------
// BM=128, BK=16, TM=8; BN/TN templated. ACT: 0=none, 1=softplus(+bias)
template <int BN, int TN, int ACT>
__global__ __launch_bounds__(256) void sgemm_tn(
    const float* __restrict__ A, const float* __restrict__ Bw,
    const float* __restrict__ bias, float* __restrict__ Cc,
    int M, int N, int Kd, int lda) {
    constexpr int BM = 128, BK = 16, TM = 8;
    constexpr int THREADS = (BM / TM) * (BN / TN);  // 256
    __shared__ float As[BK][BM + 4];
    __shared__ float Bs[BK][BN + 4];
    int tid = threadIdx.x;
    int m0 = blockIdx.y * BM;
    int n0 = blockIdx.x * BN;
    int tx = tid % (BN / TN);
    int ty = tid / (BN / TN);
    float acc[TM][TN];
#pragma unroll
    for (int i = 0; i < TM; i++)
#pragma unroll
        for (int j = 0; j < TN; j++) acc[i][j] = 0.0f;

    const int A4 = BM * BK / 4;  // 512
    const int B4 = BN * BK / 4;  // 512 or 256

    for (int k0 = 0; k0 < Kd; k0 += BK) {
        for (int i = tid; i < A4; i += THREADS) {
            int row = i >> 2, c4 = i & 3;
            float4 v = *reinterpret_cast<const float4*>(&A[(size_t)(m0 + row) * lda + k0 + c4 * 4]);
            As[c4 * 4 + 0][row] = v.x;
            As[c4 * 4 + 1][row] = v.y;
            As[c4 * 4 + 2][row] = v.z;
            As[c4 * 4 + 3][row] = v.w;
        }
        for (int i = tid; i < B4; i += THREADS) {
            int row = i >> 2, c4 = i & 3;
            float4 v = *reinterpret_cast<const float4*>(&Bw[(size_t)(n0 + row) * Kd + k0 + c4 * 4]);
            Bs[c4 * 4 + 0][row] = v.x;
            Bs[c4 * 4 + 1][row] = v.y;
            Bs[c4 * 4 + 2][row] = v.z;
            Bs[c4 * 4 + 3][row] = v.w;
        }
        __syncthreads();
#pragma unroll
        for (int kk = 0; kk < BK; kk++) {
            float a[TM], b[TN];
#pragma unroll
            for (int i = 0; i < TM; i++) a[i] = As[kk][ty * TM + i];
#pragma unroll
            for (int j = 0; j < TN; j++) b[j] = Bs[kk][tx * TN + j];
#pragma unroll
            for (int i = 0; i < TM; i++)
#pragma unroll
                for (int j = 0; j < TN; j++) acc[i][j] = fmaf(a[i], b[j], acc[i][j]);
        }
        __syncthreads();
    }

    int nbase = n0 + tx * TN;
#pragma unroll
    for (int i = 0; i < TM; i++) {
        int row = m0 + ty * TM + i;
#pragma unroll
        for (int j0 = 0; j0 < TN; j0 += 4) {
            float4 v;
            float e0 = acc[i][j0 + 0], e1 = acc[i][j0 + 1], e2 = acc[i][j0 + 2], e3 = acc[i][j0 + 3];
            if (ACT == 1) {
                e0 = softplusf_(e0 + bias[nbase + j0 + 0]);
                e1 = softplusf_(e1 + bias[nbase + j0 + 1]);
                e2 = softplusf_(e2 + bias[nbase + j0 + 2]);
                e3 = softplusf_(e3 + bias[nbase + j0 + 3]);
            }
            v.x = e0; v.y = e1; v.z = e2; v.w = e3;
            *reinterpret_cast<float4*>(&Cc[(size_t)row * N + nbase + j0]) = v;
        }
    }
}

// ---------------- depthwise causal conv (K=4) + bias + silu ----------------
__global__ __launch_bounds__(256) void conv_silu_kernel(
    const float* __restrict__ xz, const float* __restrict__ cw,
    const float* __restrict__ cb, float* __restrict__ xc) {
    int idx = blockIdx.x * blockDim.x + threadIdx.x;
    int d = idx & (DIn - 1);
    int m = idx >> 10;  // row index
    int l = m & (LSEQ - 1);
    float acc = cb[d];
    float w0 = cw[d * 4 + 0], w1 = cw[d * 4 + 1], w2 = cw[d * 4 + 2], w3 = cw[d * 4 + 3];
    const float* base = xz + (size_t)m * (2 * DIn) + d;
    if (l >= 3) acc += base[-3 * 2 * DIn] * w0;
    if (l >= 2) acc += base[-2 * 2 * DIn] * w1;
    if (l >= 1) acc += base[-1 * 2 * DIn] * w2;
    acc += base[0] * w3;
    xc[(size_t)m * DIn + d] = acc * sigmoidf_(acc);
}

// ---------------- scan phase 1: per-chunk (P, E) with h0 = 0 ----------------
__global__ __launch_bounds__(128) void scan_phase1(
    const float* __restrict__ dt, const float* __restrict__ xc,
    const float* __restrict__ dbl, const float* __restrict__ A_log_l,
    float* __restrict__ Pout, float* __restrict__ Eout) {
    int d = blockIdx.x * 128 + threadIdx.x;
    int c = blockIdx.y, b = blockIdx.z;
    float As[DSt], h[DSt], P[DSt];
#pragma unroll
    for (int s = 0; s < DSt; s++) {
        As[s] = -__expf(A_log_l[d * DSt + s]);
        h[s] = 0.0f;
        P[s] = 1.0f;
    }
    int base = b * LSEQ + c * CHL;
    for (int t = 0; t < CHL; t++) {
        int m = base + t;
        float dtv = dt[(size_t)m * DIn + d];
        float xv = xc[(size_t)m * DIn + d];
        float dtx = dtv * xv;
        const float4* bl4 = reinterpret_cast<const float4*>(&dbl[(size_t)m * 64 + 32]);
        float Bv[DSt];
#pragma unroll
        for (int q = 0; q < 4; q++) {
            float4 v = bl4[q];
            Bv[q * 4 + 0] = v.x; Bv[q * 4 + 1] = v.y; Bv[q * 4 + 2] = v.z; Bv[q * 4 + 3] = v.w;
        }
#pragma unroll
        for (int s = 0; s < DSt; s++) {
            float dA = __expf(dtv * As[s]);
            h[s] = h[s] * dA + dtx * Bv[s];
            P[s] *= dA;
        }
    }
    int p0 = ((b * NCH + c) * DSt) * DIn + d;
#pragma unroll
    for (int s = 0; s < DSt; s++) {
        Pout[p0 + s * DIn] = P[s];
        Eout[p0 + s * DIn] = h[s];
    }
}

// ---------------- scan phase 2: prefix over chunks ----------------
__global__ __launch_bounds__(256) void scan_phase2(
    const float* __restrict__ P, const float* __restrict__ E, float* __restrict__ H0) {
    int idx = blockIdx.x * blockDim.x + threadIdx.x;  // BATCH*DSt*DIn = 65536
    int d = idx & (DIn - 1);
    int s = (idx >> 10) & (DSt - 1);
    int b = idx >> 14;
    float H = 0.0f;
#pragma unroll
    for (int c = 0; c < NCH; c++) {
        int p = ((b * NCH + c) * DSt + s) * DIn + d;
        H0[p] = H;
        H = P[p] * H + E[p];
    }
}

// ---------------- scan phase 3: recompute with true h0, fused epilogue ----------------
__global__ __launch_bounds__(128) void scan_phase3(
    const float* __restrict__ dt, const float* __restrict__ xc,
    const float* __restrict__ dbl, const float* __restrict__ xz,
    const float* __restrict__ A_log_l, const float* __restrict__ Dvec,
    const float* __restrict__ H0, float* __restrict__ y) {
    int d = blockIdx.x * 128 + threadIdx.x;
    int c = blockIdx.y, b = blockIdx.z;
    float As[DSt], h[DSt];
    int p0 = ((b * NCH + c) * DSt) * DIn + d;
#pragma unroll
    for (int s = 0; s < DSt; s++) {
        As[s] = -__expf(A_log_l[d * DSt + s]);
        h[s] = H0[p0 + s * DIn];
    }
    float Dv = Dvec[d];
    int base = b * LSEQ + c * CHL;
    for (int t = 0; t < CHL; t++) {
        int m = base + t;
        float dtv = dt[(size_t)m * DIn + d];
        float xv = xc[(size_t)m * DIn + d];
        float dtx = dtv * xv;
        const float4* bl4 = reinterpret_cast<const float4*>(&dbl[(size_t)m * 64 + 32]);
        float Bv[DSt], Cv[DSt];
#pragma unroll
        for (int q = 0; q < 4; q++) {
            float4 v = bl4[q];
            Bv[q * 4 + 0] = v.x; Bv[q * 4 + 1] = v.y; Bv[q * 4 + 2] = v.z; Bv[q * 4 + 3] = v.w;
            float4 u = bl4[4 + q];
            Cv[q * 4 + 0] = u.x; Cv[q * 4 + 1] = u.y; Cv[q * 4 + 2] = u.z; Cv[q * 4 + 3] = u.w;
        }
        float yacc = 0.0f;
#pragma unroll
        for (int s = 0; s < DSt; s++) {
            float dA = __expf(dtv * As[s]);
            h[s] = h[s] * dA + dtx * Bv[s];
            yacc = fmaf(h[s], Cv[s], yacc);
        }
        yacc = fmaf(xv, Dv, yacc);
        float zv = xz[(size_t)m * (2 * DIn) + DIn + d];
        y[(size_t)m * DIn + d] = yacc * zv * sigmoidf_(zv);
    }
}

// ---------------- host ----------------
extern "C" void kernel_launch(void* const* d_in, const int* in_sizes, int n_in,
                              void* d_out, int out_size) {
    const float* x       = (const float*)d_in[0];
    const float* ln_w    = (const float*)d_in[1];
    const float* ln_b    = (const float*)d_in[2];
    const float* in_w    = (const float*)d_in[3];
    const float* conv_w  = (const float*)d_in[4];
    const float* conv_b  = (const float*)d_in[5];
    const float* xproj_w = (const float*)d_in[6];
    const float* dt_w    = (const float*)d_in[7];
    const float* dt_b    = (const float*)d_in[8];
    const float* A_log   = (const float*)d_in[9];
    const float* Dvec    = (const float*)d_in[10];
    const float* out_w   = (const float*)d_in[11];
    float* out = (float*)d_out;

    float *hn, *xz, *xc, *dbl, *dtp, *yp, *hb, *Pp, *Ep, *H0p;
    cudaGetSymbolAddress((void**)&hn, g_hn);
    cudaGetSymbolAddress((void**)&xz, g_xz);
    cudaGetSymbolAddress((void**)&xc, g_xc);
    cudaGetSymbolAddress((void**)&dbl, g_dbl);
    cudaGetSymbolAddress((void**)&dtp, g_dt);
    cudaGetSymbolAddress((void**)&yp, g_y);
    cudaGetSymbolAddress((void**)&hb, g_h);
    cudaGetSymbolAddress((void**)&Pp, g_P);
    cudaGetSymbolAddress((void**)&Ep, g_E);
    cudaGetSymbolAddress((void**)&H0p, g_H0);

    for (int layer = 0; layer < 2; layer++) {
        const float* hin = (layer == 0) ? x : hb;
        float* hout = (layer == 0) ? hb : out;

        layernorm_kernel<<<MROWS / 8, 256>>>(hin, ln_w + layer * DMdl, ln_b + layer * DMdl, hn);

        // in_proj: [16384,512] x [2048,512]^T -> [16384,2048]
        sgemm_tn<128, 8, 0><<<dim3(2 * DIn / 128, MROWS / 128), 256>>>(
            hn, in_w + (size_t)layer * 2 * DIn * DMdl, nullptr, xz,
            MROWS, 2 * DIn, DMdl, DMdl);

        conv_silu_kernel<<<MROWS * DIn / 256, 256>>>(
            xz, conv_w + layer * DIn * KCV, conv_b + layer * DIn, xc);

        // xproj: [16384,1024] x [64,1024]^T -> [16384,64]
        sgemm_tn<64, 4, 0><<<dim3(1, MROWS / 128), 256>>>(
            xc, xproj_w + (size_t)layer * 64 * DIn, nullptr, dbl,
            MROWS, 64, DIn, DIn);

        // dt: softplus( dtr[16384,32] x dt_w[1024,32]^T + dt_b ) -> [16384,1024]
        sgemm_tn<128, 8, 1><<<dim3(DIn / 128, MROWS / 128), 256>>>(
            dbl, dt_w + (size_t)layer * DIn * DTRk, dt_b + layer * DIn, dtp,
            MROWS, DIn, DTRk, 64);

        scan_phase1<<<dim3(DIn / 128, NCH, BATCH), 128>>>(
            dtp, xc, dbl, A_log + layer * DIn * DSt, Pp, Ep);
        scan_phase2<<<BATCH * DSt * DIn / 256, 256>>>(Pp, Ep, H0p);
        scan_phase3<<<dim3(DIn / 128, NCH, BATCH), 128>>>(
            dtp, xc, dbl, xz, A_log + layer * DIn * DSt, Dvec + layer * DIn, H0p, yp);

        // out_proj: [16384,1024] x [512,1024]^T -> [16384,512]
        sgemm_tn<128, 8, 0><<<dim3(DMdl / 128, MROWS / 128), 256>>>(
            yp, out_w + (size_t)layer * DMdl * DIn, nullptr, hout,
            MROWS, DMdl, DIn, DIn);
    }
}

// round 12
// speedup vs baseline: 1.2091x; 1.2091x over previous
#include <cuda_runtime.h>
#include <math.h>

#define BATCH 4
#define LSEQ 4096
#define DMdl 512
#define DIn 1024
#define DSt 16
#define DTRk 32
#define KCV 4
#define MROWS (BATCH * LSEQ)      // 16384
#define NCH 32                    // scan chunks
#define CHL (LSEQ / NCH)          // 128 steps per chunk

// ---------------- scratch (static device globals; no allocation) ----------------
__device__ float g_hn[MROWS * DMdl];          // layernorm output
__device__ float g_xz[MROWS * 2 * DIn];       // in_proj output (xq | z)
__device__ float g_xc[MROWS * DIn];           // conv+silu output
__device__ float g_dbl[MROWS * 64];           // xproj output (dtr|B|C)
__device__ float g_dt[MROWS * DIn];           // softplus(dt)
__device__ float g_y[MROWS * DIn];            // scan output (pre out_proj)
__device__ float g_h[MROWS * DMdl];           // layer output
__device__ float g_P[BATCH * NCH * DSt * DIn];
__device__ float g_E[BATCH * NCH * DSt * DIn];
__device__ float g_H0[BATCH * NCH * DSt * DIn];

__device__ __forceinline__ float sigmoidf_(float v) {
    return 1.0f / (1.0f + __expf(-v));
}
__device__ __forceinline__ float softplusf_(float v) {
    return fmaxf(v, 0.0f) + log1pf(__expf(-fabsf(v)));
}

// packed f32x2 helpers (sm_100+/sm_103a)
__device__ __forceinline__ unsigned long long pack2_(float lo, float hi) {
    unsigned long long r;
    asm("mov.b64 %0, {%1, %2};" : "=l"(r) : "f"(lo), "f"(hi));
    return r;
}
__device__ __forceinline__ void unpack2_(unsigned long long v, float& lo, float& hi) {
    asm("mov.b64 {%0, %1}, %2;" : "=f"(lo), "=f"(hi) : "l"(v));
}
__device__ __forceinline__ void fma2_(unsigned long long& d, unsigned long long a,
                                      unsigned long long b) {
    asm("fma.rn.f32x2 %0, %1, %2, %0;" : "+l"(d) : "l"(a), "l"(b));
}

// ---------------- LayerNorm: one warp per row of 512 ----------------
__global__ __launch_bounds__(256) void layernorm_kernel(
    const float* __restrict__ x, const float* __restrict__ w,
    const float* __restrict__ bvec, float* __restrict__ out) {
    int warp = threadIdx.x >> 5, lane = threadIdx.x & 31;
    int row = blockIdx.x * 8 + warp;
    const float4* xr = reinterpret_cast<const float4*>(x + (size_t)row * DMdl);
    float4 v[4];
    float s = 0.0f;
#pragma unroll
    for (int j = 0; j < 4; j++) {
        v[j] = xr[j * 32 + lane];
        s += v[j].x + v[j].y + v[j].z + v[j].w;
    }
#pragma unroll
    for (int m = 16; m; m >>= 1) s += __shfl_xor_sync(0xffffffffu, s, m);
    float mean = s * (1.0f / DMdl);
    float vs = 0.0f;
#pragma unroll
    for (int j = 0; j < 4; j++) {
        float a = v[j].x - mean, b = v[j].y - mean, c = v[j].z - mean, d = v[j].w - mean;
        vs += a * a + b * b + c * c + d * d;
    }
#pragma unroll
    for (int m = 16; m; m >>= 1) vs += __shfl_xor_sync(0xffffffffu, vs, m);
    float rstd = rsqrtf(vs * (1.0f / DMdl) + 1e-5f);
    const float4* w4 = reinterpret_cast<const float4*>(w);
    const float4* b4 = reinterpret_cast<const float4*>(bvec);
    float4* o4 = reinterpret_cast<float4*>(out + (size_t)row * DMdl);
#pragma unroll
    for (int j = 0; j < 4; j++) {
        float4 wv = w4[j * 32 + lane], bv = b4[j * 32 + lane], r;
        r.x = (v[j].x - mean) * rstd * wv.x + bv.x;
        r.y = (v[j].y - mean) * rstd * wv.y + bv.y;
        r.z = (v[j].z - mean) * rstd * wv.z + bv.z;
        r.w = (v[j].w - mean) * rstd * wv.w + bv.w;
        o4[j * 32 + lane] = r;
    }
}

// ---------------- SGEMM (TN) with packed f32x2 FMA + double-buffered smem ----------------
// C[m,n] = sum_k A[m,k]*B[n,k]. Accumulators packed along M (pairs of rows).
// Single __syncthreads per k-tile; STS overlapped with FFMA of the other buffer.
template <int BM, int BN, int TM, int TN, int ACT>
__global__ __launch_bounds__(256) void sgemm_tn_x2(
    const float* __restrict__ A, const float* __restrict__ Bw,
    const float* __restrict__ bias, float* __restrict__ Cc,
    int M, int N, int Kd, int lda) {
    constexpr int BK = 16;
    constexpr int THREADS = (BM / TM) * (BN / TN);  // must be 256
    constexpr int A_LD = BM * BK / 4 / THREADS;     // float4 per thread for A
    constexpr int B_LD = BN * BK / 4 / THREADS;
    constexpr int TMH = TM / 2;

    __shared__ float As[2][BK][BM + 4];
    __shared__ float Bs[2][BK][BN + 4];

    int tid = threadIdx.x;
    int m0 = blockIdx.y * BM;
    int n0 = blockIdx.x * BN;
    int tx = tid % (BN / TN);
    int ty = tid / (BN / TN);

    unsigned long long acc[TMH][TN];
#pragma unroll
    for (int i = 0; i < TMH; i++)
#pragma unroll
        for (int j = 0; j < TN; j++) acc[i][j] = 0ULL;

    float4 pa[A_LD], pb[B_LD];

    auto ldg_tiles = [&](int k0) {
#pragma unroll
        for (int t = 0; t < A_LD; t++) {
            int i = tid + t * THREADS;
            int row = i >> 2, c4 = i & 3;
            pa[t] = *reinterpret_cast<const float4*>(
                &A[(size_t)(m0 + row) * lda + k0 + c4 * 4]);
        }
#pragma unroll
        for (int t = 0; t < B_LD; t++) {
            int i = tid + t * THREADS;
            int row = i >> 2, c4 = i & 3;
            pb[t] = *reinterpret_cast<const float4*>(
                &Bw[(size_t)(n0 + row) * Kd + k0 + c4 * 4]);
        }
    };
    auto sts_tiles = [&](int buf) {
#pragma unroll
        for (int t = 0; t < A_LD; t++) {
            int i = tid + t * THREADS;
            int row = i >> 2, c4 = i & 3;
            As[buf][c4 * 4 + 0][row] = pa[t].x;
            As[buf][c4 * 4 + 1][row] = pa[t].y;
            As[buf][c4 * 4 + 2][row] = pa[t].z;
            As[buf][c4 * 4 + 3][row] = pa[t].w;
        }
#pragma unroll
        for (int t = 0; t < B_LD; t++) {
            int i = tid + t * THREADS;
            int row = i >> 2, c4 = i & 3;
            Bs[buf][c4 * 4 + 0][row] = pb[t].x;
            Bs[buf][c4 * 4 + 1][row] = pb[t].y;
            Bs[buf][c4 * 4 + 2][row] = pb[t].z;
            Bs[buf][c4 * 4 + 3][row] = pb[t].w;
        }
    };
    auto compute_tile = [&](int buf) {
#pragma unroll
        for (int kk = 0; kk < BK; kk++) {
            unsigned long long apair[TMH], bb[TN];
#pragma unroll
            for (int i = 0; i < TMH; i++)
                apair[i] = *reinterpret_cast<const unsigned long long*>(
                    &As[buf][kk][ty * TM + 2 * i]);
#pragma unroll
            for (int j = 0; j < TN; j++) {
                float b = Bs[buf][kk][tx * TN + j];
                bb[j] = pack2_(b, b);
            }
#pragma unroll
            for (int i = 0; i < TMH; i++)
#pragma unroll
                for (int j = 0; j < TN; j++) fma2_(acc[i][j], apair[i], bb[j]);
        }
    };

    ldg_tiles(0);
    sts_tiles(0);
    __syncthreads();
    int buf = 0;
    for (int k0 = BK; k0 <= Kd - BK; k0 += BK) {
        ldg_tiles(k0);
        compute_tile(buf);
        sts_tiles(buf ^ 1);
        __syncthreads();
        buf ^= 1;
    }
    compute_tile(buf);

    int nbase = n0 + tx * TN;
#pragma unroll
    for (int i = 0; i < TMH; i++) {
        float lo[TN], hi[TN];
#pragma unroll
        for (int j = 0; j < TN; j++) unpack2_(acc[i][j], lo[j], hi[j]);
        if (ACT == 1) {
#pragma unroll
            for (int j = 0; j < TN; j++) {
                float bs = bias[nbase + j];
                lo[j] = softplusf_(lo[j] + bs);
                hi[j] = softplusf_(hi[j] + bs);
            }
        }
        int row0 = m0 + ty * TM + 2 * i;
#pragma unroll
        for (int j0 = 0; j0 < TN; j0 += 4) {
            float4 v0 = {lo[j0], lo[j0 + 1], lo[j0 + 2], lo[j0 + 3]};
            float4 v1 = {hi[j0], hi[j0 + 1], hi[j0 + 2], hi[j0 + 3]};
            *reinterpret_cast<float4*>(&Cc[(size_t)row0 * N + nbase + j0]) = v0;
            *reinterpret_cast<float4*>(&Cc[(size_t)(row0 + 1) * N + nbase + j0]) = v1;
        }
    }
}

// ---------------- depthwise causal conv (K=4) + bias + silu ----------------
__global__ __launch_bounds__(256) void conv_silu_kernel(
    const float* __restrict__ xz, const float* __restrict__ cw,
    const float* __restrict__ cb, float* __restrict__ xc) {
    int idx = blockIdx.x * blockDim.x + threadIdx.x;
    int d = idx & (DIn - 1);
    int m = idx >> 10;
    int l = m & (LSEQ - 1);
    float acc = cb[d];
    float w0 = cw[d * 4 + 0], w1 = cw[d * 4 + 1], w2 = cw[d * 4 + 2], w3 = cw[d * 4 + 3];
    const float* base = xz + (size_t)m * (2 * DIn) + d;
    if (l >= 3) acc += base[-3 * 2 * DIn] * w0;
    if (l >= 2) acc += base[-2 * 2 * DIn] * w1;
    if (l >= 1) acc += base[-1 * 2 * DIn] * w2;
    acc += base[0] * w3;
    xc[(size_t)m * DIn + d] = acc * sigmoidf_(acc);
}

// ---------------- scan phase 1: per-chunk (P, E) with h0 = 0 ----------------
__global__ __launch_bounds__(128) void scan_phase1(
    const float* __restrict__ dt, const float* __restrict__ xc,
    const float* __restrict__ dbl, const float* __restrict__ A_log_l,
    float* __restrict__ Pout, float* __restrict__ Eout) {
    int d = blockIdx.x * 128 + threadIdx.x;
    int c = blockIdx.y, b = blockIdx.z;
    float As[DSt], h[DSt], P[DSt];
#pragma unroll
    for (int s = 0; s < DSt; s++) {
        As[s] = -__expf(A_log_l[d * DSt + s]);
        h[s] = 0.0f;
        P[s] = 1.0f;
    }
    int base = b * LSEQ + c * CHL;
    for (int t = 0; t < CHL; t++) {
        int m = base + t;
        float dtv = dt[(size_t)m * DIn + d];
        float xv = xc[(size_t)m * DIn + d];
        float dtx = dtv * xv;
        const float4* bl4 = reinterpret_cast<const float4*>(&dbl[(size_t)m * 64 + 32]);
        float Bv[DSt];
#pragma unroll
        for (int q = 0; q < 4; q++) {
            float4 v = bl4[q];
            Bv[q * 4 + 0] = v.x; Bv[q * 4 + 1] = v.y; Bv[q * 4 + 2] = v.z; Bv[q * 4 + 3] = v.w;
        }
#pragma unroll
        for (int s = 0; s < DSt; s++) {
            float dA = __expf(dtv * As[s]);
            h[s] = h[s] * dA + dtx * Bv[s];
            P[s] *= dA;
        }
    }
    int p0 = ((b * NCH + c) * DSt) * DIn + d;
#pragma unroll
    for (int s = 0; s < DSt; s++) {
        Pout[p0 + s * DIn] = P[s];
        Eout[p0 + s * DIn] = h[s];
    }
}

// ---------------- scan phase 2: prefix over chunks ----------------
__global__ __launch_bounds__(256) void scan_phase2(
    const float* __restrict__ P, const float* __restrict__ E, float* __restrict__ H0) {
    int idx = blockIdx.x * blockDim.x + threadIdx.x;
    int d = idx & (DIn - 1);
    int s = (idx >> 10) & (DSt - 1);
    int b = idx >> 14;
    float H = 0.0f;
#pragma unroll
    for (int c = 0; c < NCH; c++) {
        int p = ((b * NCH + c) * DSt + s) * DIn + d;
        H0[p] = H;
        H = P[p] * H + E[p];
    }
}

// ---------------- scan phase 3: recompute with true h0, fused epilogue ----------------
__global__ __launch_bounds__(128) void scan_phase3(
    const float* __restrict__ dt, const float* __restrict__ xc,
    const float* __restrict__ dbl, const float* __restrict__ xz,
    const float* __restrict__ A_log_l, const float* __restrict__ Dvec,
    const float* __restrict__ H0, float* __restrict__ y) {
    int d = blockIdx.x * 128 + threadIdx.x;
    int c = blockIdx.y, b = blockIdx.z;
    float As[DSt], h[DSt];
    int p0 = ((b * NCH + c) * DSt) * DIn + d;
#pragma unroll
    for (int s = 0; s < DSt; s++) {
        As[s] = -__expf(A_log_l[d * DSt + s]);
        h[s] = H0[p0 + s * DIn];
    }
    float Dv = Dvec[d];
    int base = b * LSEQ + c * CHL;
    for (int t = 0; t < CHL; t++) {
        int m = base + t;
        float dtv = dt[(size_t)m * DIn + d];
        float xv = xc[(size_t)m * DIn + d];
        float dtx = dtv * xv;
        const float4* bl4 = reinterpret_cast<const float4*>(&dbl[(size_t)m * 64 + 32]);
        float Bv[DSt], Cv[DSt];
#pragma unroll
        for (int q = 0; q < 4; q++) {
            float4 v = bl4[q];
            Bv[q * 4 + 0] = v.x; Bv[q * 4 + 1] = v.y; Bv[q * 4 + 2] = v.z; Bv[q * 4 + 3] = v.w;
            float4 u = bl4[4 + q];
            Cv[q * 4 + 0] = u.x; Cv[q * 4 + 1] = u.y; Cv[q * 4 + 2] = u.z; Cv[q * 4 + 3] = u.w;
        }
        float yacc = 0.0f;
#pragma unroll
        for (int s = 0; s < DSt; s++) {
            float dA = __expf(dtv * As[s]);
            h[s] = h[s] * dA + dtx * Bv[s];
            yacc = fmaf(h[s], Cv[s], yacc);
        }
        yacc = fmaf(xv, Dv, yacc);
        float zv = xz[(size_t)m * (2 * DIn) + DIn + d];
        y[(size_t)m * DIn + d] = yacc * zv * sigmoidf_(zv);
    }
}

// ---------------- host ----------------
extern "C" void kernel_launch(void* const* d_in, const int* in_sizes, int n_in,
                              void* d_out, int out_size) {
    const float* x       = (const float*)d_in[0];
    const float* ln_w    = (const float*)d_in[1];
    const float* ln_b    = (const float*)d_in[2];
    const float* in_w    = (const float*)d_in[3];
    const float* conv_w  = (const float*)d_in[4];
    const float* conv_b  = (const float*)d_in[5];
    const float* xproj_w = (const float*)d_in[6];
    const float* dt_w    = (const float*)d_in[7];
    const float* dt_b    = (const float*)d_in[8];
    const float* A_log   = (const float*)d_in[9];
    const float* Dvec    = (const float*)d_in[10];
    const float* out_w   = (const float*)d_in[11];
    float* out = (float*)d_out;

    float *hn, *xz, *xc, *dbl, *dtp, *yp, *hb, *Pp, *Ep, *H0p;
    cudaGetSymbolAddress((void**)&hn, g_hn);
    cudaGetSymbolAddress((void**)&xz, g_xz);
    cudaGetSymbolAddress((void**)&xc, g_xc);
    cudaGetSymbolAddress((void**)&dbl, g_dbl);
    cudaGetSymbolAddress((void**)&dtp, g_dt);
    cudaGetSymbolAddress((void**)&yp, g_y);
    cudaGetSymbolAddress((void**)&hb, g_h);
    cudaGetSymbolAddress((void**)&Pp, g_P);
    cudaGetSymbolAddress((void**)&Ep, g_E);
    cudaGetSymbolAddress((void**)&H0p, g_H0);

    for (int layer = 0; layer < 2; layer++) {
        const float* hin = (layer == 0) ? x : hb;
        float* hout = (layer == 0) ? hb : out;

        layernorm_kernel<<<MROWS / 8, 256>>>(hin, ln_w + layer * DMdl, ln_b + layer * DMdl, hn);

        // in_proj: [16384,512] x [2048,512]^T -> [16384,2048]
        sgemm_tn_x2<128, 128, 8, 8, 0><<<dim3(2 * DIn / 128, MROWS / 128), 256>>>(
            hn, in_w + (size_t)layer * 2 * DIn * DMdl, nullptr, xz,
            MROWS, 2 * DIn, DMdl, DMdl);

        conv_silu_kernel<<<MROWS * DIn / 256, 256>>>(
            xz, conv_w + layer * DIn * KCV, conv_b + layer * DIn, xc);

        // xproj: [16384,1024] x [64,1024]^T -> [16384,64]  (64x64 tiles, 256 blocks)
        sgemm_tn_x2<64, 64, 4, 4, 0><<<dim3(1, MROWS / 64), 256>>>(
            xc, xproj_w + (size_t)layer * 64 * DIn, nullptr, dbl,
            MROWS, 64, DIn, DIn);

        // dt: softplus( dtr[16384,32] x dt_w[1024,32]^T + dt_b ) -> [16384,1024]
        sgemm_tn_x2<128, 128, 8, 8, 1><<<dim3(DIn / 128, MROWS / 128), 256>>>(
            dbl, dt_w + (size_t)layer * DIn * DTRk, dt_b + layer * DIn, dtp,
            MROWS, DIn, DTRk, 64);

        scan_phase1<<<dim3(DIn / 128, NCH, BATCH), 128>>>(
            dtp, xc, dbl, A_log + layer * DIn * DSt, Pp, Ep);
        scan_phase2<<<BATCH * DSt * DIn / 256, 256>>>(Pp, Ep, H0p);
        scan_phase3<<<dim3(DIn / 128, NCH, BATCH), 128>>>(
            dtp, xc, dbl, xz, A_log + layer * DIn * DSt, Dvec + layer * DIn, H0p, yp);

        // out_proj: [16384,1024] x [512,1024]^T -> [16384,512]
        sgemm_tn_x2<128, 128, 8, 8, 0><<<dim3(DMdl / 128, MROWS / 128), 256>>>(
            yp, out_w + (size_t)layer * DMdl * DIn, nullptr, hout,
            MROWS, DMdl, DIn, DIn);
    }
}